// round 2
// baseline (speedup 1.0000x reference)
#include <cuda_runtime.h>

#define HIDDEN 128
#define LOG2E 1.4426950408889634f
#define LN2   0.6931471805599453f

// Sphere tracing with extended-space SDF.
// softplus computed in log2 domain: weights pre-scaled by log2(e), W2 by ln(2).
// c_j = pivot . W1'_j + b1'_j is iteration- and ray-invariant -> precomputed in smem.
__global__ __launch_bounds__(128)
void raymarch_kernel(const float* __restrict__ r,       // [N,4]
                     const float* __restrict__ pivot,   // [3]
                     const float* __restrict__ W1,      // [3,128] row-major
                     const float* __restrict__ b1,      // [128]
                     const float* __restrict__ W2,      // [128]
                     const float* __restrict__ b2,      // [1]
                     const int*   __restrict__ n_iter_p,
                     float* __restrict__ out,           // [N,3]
                     int N)
{
    __shared__ float4 q[HIDDEN];   // (w0', w1', w2', c) all scaled by log2(e)
    __shared__ float  w2s[HIDDEN]; // W2 * ln(2)
    __shared__ float  piv[3];

    const int tid = threadIdx.x;
    if (tid < 3) piv[tid] = pivot[tid];
    {
        const int j = tid;  // blockDim.x == 128 == HIDDEN
        float w0 = W1[0 * HIDDEN + j] * LOG2E;
        float w1 = W1[1 * HIDDEN + j] * LOG2E;
        float w2 = W1[2 * HIDDEN + j] * LOG2E;
        float p0 = pivot[0], p1 = pivot[1], p2 = pivot[2];
        float c = fmaf(p2, w2, fmaf(p1, w1, fmaf(p0, w0, b1[j] * LOG2E)));
        q[j] = make_float4(w0, w1, w2, c);
        w2s[j] = W2[j] * LN2;
    }
    __syncthreads();

    const int i = blockIdx.x * blockDim.x + tid;
    if (i >= N) return;

    float4 rv = reinterpret_cast<const float4*>(r)[i];
    float inv = rsqrtf(fmaf(rv.x, rv.x, fmaf(rv.y, rv.y, fmaf(rv.z, rv.z, rv.w * rv.w))));
    float rn0 = rv.x * inv;
    float rn1 = rv.y * inv;
    float rn2 = rv.z * inv;
    float rn3 = rv.w * inv;

    const int n_iter = *n_iter_p;
    const float b2v = *b2;
    float alpha = 0.0f;

    for (int it = 0; it < n_iter; ++it) {
        float a1 = alpha * rn1;
        float a2 = alpha * rn2;
        float a3 = alpha * rn3;
        float s = b2v;
        #pragma unroll
        for (int j = 0; j < HIDDEN; ++j) {
            float4 Q = q[j];
            // t = log2(e) * (x . W1_j + b1_j), x = pivot + alpha*rn  (pivot folded into Q.w)
            float t = fmaf(a3, Q.z, fmaf(a2, Q.y, fmaf(a1, Q.x, Q.w)));
            // softplus stable in log2 domain: max(t,0) + log2(1 + 2^{-|t|})
            float u;
            asm("ex2.approx.f32 %0, %1;" : "=f"(u) : "f"(-fabsf(t)));
            float v = 1.0f + u;
            float l;
            asm("lg2.approx.f32 %0, %1;" : "=f"(l) : "f"(v));
            float h = fmaxf(t, 0.0f) + l;   // = softplus(z) / ln(2)
            s = fmaf(h, w2s[j], s);         // ln(2) folded into w2s
        }
        // extended SDF + alpha update
        float a  = fabsf(s);
        float x0 = alpha * rn0;             // pivot_ext[0] == 0
        float ext = fmaxf(fmaxf(s, x0 - a), -(a + x0));
        alpha -= ext;
    }

    out[3 * i + 0] = fmaf(alpha, rn1, piv[0]);
    out[3 * i + 1] = fmaf(alpha, rn2, piv[1]);
    out[3 * i + 2] = fmaf(alpha, rn3, piv[2]);
}

extern "C" void kernel_launch(void* const* d_in, const int* in_sizes, int n_in,
                              void* d_out, int out_size)
{
    const float* r     = (const float*)d_in[0];
    const float* pivot = (const float*)d_in[1];
    const float* W1    = (const float*)d_in[2];
    const float* b1    = (const float*)d_in[3];
    const float* W2    = (const float*)d_in[4];
    const float* b2    = (const float*)d_in[5];
    const int*   nit   = (const int*)d_in[6];

    int N = in_sizes[0] / 4;  // r is [N,4]
    int threads = 128;
    int blocks = (N + threads - 1) / threads;
    raymarch_kernel<<<blocks, threads>>>(r, pivot, W1, b1, W2, b2, nit, (float*)d_out, N);
}

// round 5
// speedup vs baseline: 5.7414x; 5.7414x over previous
#include <cuda_runtime.h>

#define HIDDEN 128
#define LOG2E 1.4426950408889634f
#define LN2   0.6931471805599453f

// Sphere tracing with extended-space SDF.
// softplus in log2 domain: W1/b1 pre-scaled by log2(e), W2 by ln(2).
// c_j = pivot . W1'_j + b1'_j is ray/iteration invariant -> precomputed in smem.
// R2 change: unroll 8 (was 128) + reg cap via launch_bounds to kill spills / raise occupancy.
__global__ __launch_bounds__(128, 6)
void raymarch_kernel(const float* __restrict__ r,       // [N,4]
                     const float* __restrict__ pivot,   // [3]
                     const float* __restrict__ W1,      // [3,128] row-major
                     const float* __restrict__ b1,      // [128]
                     const float* __restrict__ W2,      // [128]
                     const float* __restrict__ b2,      // [1]
                     const int*   __restrict__ n_iter_p,
                     float* __restrict__ out,           // [N,3]
                     int N)
{
    __shared__ float4 q[HIDDEN];   // (w0', w1', w2', c) all scaled by log2(e)
    __shared__ float  w2s[HIDDEN]; // W2 * ln(2)
    __shared__ float  piv[3];

    const int tid = threadIdx.x;
    if (tid < 3) piv[tid] = pivot[tid];
    {
        const int j = tid;  // blockDim.x == 128 == HIDDEN
        float w0 = W1[0 * HIDDEN + j] * LOG2E;
        float w1 = W1[1 * HIDDEN + j] * LOG2E;
        float w2 = W1[2 * HIDDEN + j] * LOG2E;
        float p0 = pivot[0], p1 = pivot[1], p2 = pivot[2];
        float c = fmaf(p2, w2, fmaf(p1, w1, fmaf(p0, w0, b1[j] * LOG2E)));
        q[j] = make_float4(w0, w1, w2, c);
        w2s[j] = W2[j] * LN2;
    }
    __syncthreads();

    const int i = blockIdx.x * blockDim.x + tid;
    if (i >= N) return;

    float4 rv = reinterpret_cast<const float4*>(r)[i];
    float inv = rsqrtf(fmaf(rv.x, rv.x, fmaf(rv.y, rv.y, fmaf(rv.z, rv.z, rv.w * rv.w))));
    float rn0 = rv.x * inv;
    float rn1 = rv.y * inv;
    float rn2 = rv.z * inv;
    float rn3 = rv.w * inv;

    const int n_iter = *n_iter_p;
    const float b2v = *b2;
    float alpha = 0.0f;

    for (int it = 0; it < n_iter; ++it) {
        float a1 = alpha * rn1;
        float a2 = alpha * rn2;
        float a3 = alpha * rn3;
        float s0 = b2v, s1 = 0.0f;
        #pragma unroll 8
        for (int j = 0; j < HIDDEN; j += 2) {
            float4 Qa = q[j];
            float4 Qb = q[j + 1];
            float ta = fmaf(a3, Qa.z, fmaf(a2, Qa.y, fmaf(a1, Qa.x, Qa.w)));
            float tb = fmaf(a3, Qb.z, fmaf(a2, Qb.y, fmaf(a1, Qb.x, Qb.w)));
            float ua, ub;
            asm("ex2.approx.f32 %0, %1;" : "=f"(ua) : "f"(-fabsf(ta)));
            asm("ex2.approx.f32 %0, %1;" : "=f"(ub) : "f"(-fabsf(tb)));
            float la, lb;
            asm("lg2.approx.f32 %0, %1;" : "=f"(la) : "f"(1.0f + ua));
            asm("lg2.approx.f32 %0, %1;" : "=f"(lb) : "f"(1.0f + ub));
            float ha = fmaxf(ta, 0.0f) + la;   // softplus(z)/ln2
            float hb = fmaxf(tb, 0.0f) + lb;
            s0 = fmaf(ha, w2s[j], s0);
            s1 = fmaf(hb, w2s[j + 1], s1);
        }
        float s = s0 + s1;
        // extended SDF + alpha update
        float a  = fabsf(s);
        float x0 = alpha * rn0;             // pivot_ext[0] == 0
        float ext = fmaxf(fmaxf(s, x0 - a), -(a + x0));
        alpha -= ext;
    }

    out[3 * i + 0] = fmaf(alpha, rn1, piv[0]);
    out[3 * i + 1] = fmaf(alpha, rn2, piv[1]);
    out[3 * i + 2] = fmaf(alpha, rn3, piv[2]);
}

extern "C" void kernel_launch(void* const* d_in, const int* in_sizes, int n_in,
                              void* d_out, int out_size)
{
    const float* r     = (const float*)d_in[0];
    const float* pivot = (const float*)d_in[1];
    const float* W1    = (const float*)d_in[2];
    const float* b1    = (const float*)d_in[3];
    const float* W2    = (const float*)d_in[4];
    const float* b2    = (const float*)d_in[5];
    const int*   nit   = (const int*)d_in[6];

    int N = in_sizes[0] / 4;  // r is [N,4]
    int threads = 128;
    int blocks = (N + threads - 1) / threads;
    raymarch_kernel<<<blocks, threads>>>(r, pivot, W1, b1, W2, b2, nit, (float*)d_out, N);
}